// round 5
// baseline (speedup 1.0000x reference)
#include <cuda_runtime.h>
#include <math.h>

#define N_NODES 20000
#define K_NB    32
#define D_DIM   128
#define PAD     132   // padded row stride (floats)

// ---------------- scratch (device globals: allocation-free) ----------------
__device__ float g_tsf[(size_t)N_NODES * D_DIM];   // self_feats @ self_weights
__device__ float g_tself[N_NODES];                 // self_vecs . gate_self_w

__device__ __forceinline__ float sigmoid_tanh(float x) {
    float t;
    asm("tanh.approx.f32 %0, %1;" : "=f"(t) : "f"(0.5f * x));
    return fmaf(0.5f, t, 0.5f);
}

__device__ __forceinline__ unsigned f2tf32(float x) {
    unsigned u;
    asm("cvt.rna.tf32.f32 %0, %1;" : "=r"(u) : "f"(x));
    return u;
}

__device__ __forceinline__ void cp16(void* dst, const void* src) {
    unsigned sa = (unsigned)__cvta_generic_to_shared(dst);
    asm volatile("cp.async.cg.shared.global [%0], [%1], 16;\n" :: "r"(sa), "l"(src));
}
__device__ __forceinline__ void cp_commit() {
    asm volatile("cp.async.commit_group;\n");
}
__device__ __forceinline__ void cp_wait0() {
    asm volatile("cp.async.wait_group 0;\n");
}

__device__ __forceinline__ void mma_tf32(float& c0, float& c1, float& c2, float& c3,
                                         unsigned a0, unsigned a1, unsigned a2, unsigned a3,
                                         unsigned b0, unsigned b1) {
    asm volatile(
        "mma.sync.aligned.m16n8k8.row.col.f32.tf32.tf32.f32 "
        "{%0,%1,%2,%3}, {%4,%5,%6,%7}, {%8,%9}, {%0,%1,%2,%3};\n"
        : "+f"(c0), "+f"(c1), "+f"(c2), "+f"(c3)
        : "r"(a0), "r"(a1), "r"(a2), "r"(a3), "r"(b0), "r"(b1));
}

// ---------------- kernel 1: tself[n] = dot(self_vecs[n], gate_self_w) ------
__global__ void k_tself(const float* __restrict__ self_vecs,
                        const float* __restrict__ gws) {
    int gtid = blockIdx.x * blockDim.x + threadIdx.x;
    int node = gtid >> 5;
    int lane = gtid & 31;
    if (node >= N_NODES) return;
    const float4* sv = (const float4*)(self_vecs + (size_t)node * D_DIM);
    const float4* gw = (const float4*)gws;
    float4 a = sv[lane];
    float4 b = __ldg(&gw[lane]);
    float s = a.x * b.x + a.y * b.y + a.z * b.z + a.w * b.w;
    #pragma unroll
    for (int o = 16; o > 0; o >>= 1) s += __shfl_down_sync(0xffffffffu, s, o);
    if (lane == 0) g_tself[node] = s;
}

// ---------------- kernel 2: tsf = self_feats @ self_weights ----------------
#define TSF_NODES 16
__global__ void k_tsf(const float* __restrict__ self_feats,
                      const float* __restrict__ Ws) {
    extern __shared__ float sm[];
    float* Wsh = sm;                       // 128*128
    float* sfs = sm + D_DIM * D_DIM;       // 16*128
    int t = threadIdx.x;

    for (int i = t; i < (D_DIM * D_DIM) / 4; i += 256)
        ((float4*)Wsh)[i] = ((const float4*)Ws)[i];

    int nbase = blockIdx.x * TSF_NODES;
    const float4* gsf = (const float4*)(self_feats + (size_t)nbase * D_DIM);
    for (int i = t; i < (TSF_NODES * D_DIM) / 4; i += 256)
        ((float4*)sfs)[i] = gsf[i];
    __syncthreads();

    int e = t & 127;
    int g = t >> 7;
    float acc[8];
    #pragma unroll
    for (int m = 0; m < 8; m++) acc[m] = 0.0f;

    #pragma unroll 4
    for (int d = 0; d < D_DIM; d++) {
        float w = Wsh[d * D_DIM + e];
        #pragma unroll
        for (int m = 0; m < 8; m++)
            acc[m] = fmaf(w, sfs[(g * 8 + m) * D_DIM + d], acc[m]);
    }
    #pragma unroll
    for (int m = 0; m < 8; m++)
        g_tsf[(size_t)(nbase + g * 8 + m) * D_DIM + e] = acc[m];
}

// ---------------- kernel 3: main fused aggregator --------------------------
// 512 threads = 16 warps, warp grid 2(M) x 8(N). Per iteration: 2 nodes =
// 64 rows(M) x 128 cols(N), K=128. Warp (wm, wn) owns node p*2+wm,
// cols [wn*16, wn*16+16). Bf[16][2][2] = 64 regs: no spill.
__global__ void __launch_bounds__(512, 1)
k_main(const float* __restrict__ neigh,
       const float* __restrict__ link,
       const float* __restrict__ probs,
       const float* __restrict__ gwn,
       const float* __restrict__ gwl,
       const float* __restrict__ Wl,
       float* __restrict__ out) {
    extern __shared__ float sm[];
    float* lvb0 = sm;                           // 64*132
    float* lvb1 = lvb0 + 64 * PAD;
    float* nvb0 = lvb1 + 64 * PAD;
    float* nvb1 = nvb0 + 64 * PAD;
    float* csh  = nvb1 + 64 * PAD;              // 64
    float* gwns = csh + 64;                     // 128
    float* gwls = gwns + D_DIM;                 // 128

    int t = threadIdx.x;
    int warp = t >> 5, lane = t & 31;
    int wm = warp >> 3, wn = warp & 7;          // 2 x 8
    int lp = lane >> 2;                          // 0..7
    int lq = lane & 3;                           // 0..3

    if (t < D_DIM) { gwns[t] = gwn[t]; gwls[t] = gwl[t]; }

    // ---- B fragments (loop-invariant, 64 regs):
    // Bf[ks][ns][0] = tf32(Wl[ks*8+lq][wn*16+ns*8+lp]), [1] = k+4
    unsigned Bf[16][2][2];
    {
        int ncol = wn * 16 + lp;
        #pragma unroll
        for (int ks = 0; ks < 16; ks++)
            #pragma unroll
            for (int ns = 0; ns < 2; ns++) {
                Bf[ks][ns][0] = f2tf32(__ldg(&Wl[(ks * 8 + lq) * D_DIM + ncol + ns * 8]));
                Bf[ks][ns][1] = f2tf32(__ldg(&Wl[(ks * 8 + lq + 4) * D_DIM + ncol + ns * 8]));
            }
    }

    float* lvbuf[2] = {lvb0, lvb1};
    float* nvbuf[2] = {nvb0, nvb1};

    // prologue: first tile -> buffer 0  (64 rows x 32 float4-chunks = 2048)
    {
        int p0 = blockIdx.x;
        if (p0 < N_NODES / 2) {
            #pragma unroll
            for (int j = 0; j < 4; j++) {
                int idx = t + j * 512;
                int row = idx >> 5, c4 = idx & 31;
                size_t gb = (((size_t)p0 * 64 + row) << 7) + c4 * 4;
                cp16(lvb0 + row * PAD + c4 * 4, link + gb);
                cp16(nvb0 + row * PAD + c4 * 4, neigh + gb);
            }
        }
        cp_commit();
    }

    int kk = t >> 3, sub = t & 7;               // gate mapping: 64 rows x 8 subs
    int buf = 0;
    for (int p = blockIdx.x; p < N_NODES / 2; p += gridDim.x) {
        // ---- early prefetch of per-node scalars (cover LDG latency)
        float2 ts_pre[2];
        if (lane < 4) {
            int node = p * 2 + wm;
            #pragma unroll
            for (int ns = 0; ns < 2; ns++)
                ts_pre[ns] = *(const float2*)&g_tsf[(size_t)node * D_DIM +
                                                    wn * 16 + ns * 8 + lane * 2];
        }
        float pr_pre = 0.0f, tslf_pre = 0.0f;
        if (sub == 0) {
            pr_pre = __ldg(&probs[(size_t)p * 64 + kk]);
            tslf_pre = g_tself[p * 2 + (kk >> 5)];
        }

        cp_wait0();
        __syncthreads();                          // tile ready; prev reads done

        // ---- kick next tile into other buffer
        int pn = p + gridDim.x;
        if (pn < N_NODES / 2) {
            float* ld = lvbuf[buf ^ 1];
            float* nd_ = nvbuf[buf ^ 1];
            #pragma unroll
            for (int j = 0; j < 4; j++) {
                int idx = t + j * 512;
                int row = idx >> 5, c4 = idx & 31;
                size_t gb = (((size_t)pn * 64 + row) << 7) + c4 * 4;
                cp16(ld + row * PAD + c4 * 4, link + gb);
                cp16(nd_ + row * PAD + c4 * 4, neigh + gb);
            }
        }
        cp_commit();

        const float* lvs = lvbuf[buf];
        const float* nvs = nvbuf[buf];

        // ---- gate coefficients c[kk] = sigmoid(tself + nv.gwn + lv.gwl)/(prob*K)
        // float4 loads, conflict-free (bank groups 4*kk + 16*(sub&1))
        {
            const float4* lrow = (const float4*)(lvs + kk * PAD + sub * 16);
            const float4* nrow = (const float4*)(nvs + kk * PAD + sub * 16);
            const float4* gl = (const float4*)(gwls + sub * 16);
            const float4* gn = (const float4*)(gwns + sub * 16);
            float s = 0.0f;
            #pragma unroll
            for (int i = 0; i < 4; i++) {
                float4 a = lrow[i], b = gl[i];
                s = fmaf(a.x, b.x, s); s = fmaf(a.y, b.y, s);
                s = fmaf(a.z, b.z, s); s = fmaf(a.w, b.w, s);
                float4 c = nrow[i], d = gn[i];
                s = fmaf(c.x, d.x, s); s = fmaf(c.y, d.y, s);
                s = fmaf(c.z, d.z, s); s = fmaf(c.w, d.w, s);
            }
            s += __shfl_down_sync(0xffffffffu, s, 1, 8);
            s += __shfl_down_sync(0xffffffffu, s, 2, 8);
            s += __shfl_down_sync(0xffffffffu, s, 4, 8);
            if (sub == 0) {
                float g = sigmoid_tanh(tslf_pre + s);
                csh[kk] = __fdividef(g, pr_pre) * (1.0f / (float)K_NB);
            }
        }
        __syncthreads();                          // csh visible

        // ---- tensor-core GEMM: rows wm*32..+32, cols wn*16..+16, K=128
        float acc[2][2][4];
        #pragma unroll
        for (int m = 0; m < 2; m++)
            #pragma unroll
            for (int ns = 0; ns < 2; ns++)
                acc[m][ns][0] = acc[m][ns][1] = acc[m][ns][2] = acc[m][ns][3] = 0.0f;

        int rbase = wm * 32 + lp;
        const unsigned* r0 = (const unsigned*)(lvs + rbase * PAD);          // lp
        const unsigned* r1 = (const unsigned*)(lvs + (rbase + 8) * PAD);    // +8
        const unsigned* r2 = (const unsigned*)(lvs + (rbase + 16) * PAD);   // +16
        const unsigned* r3 = (const unsigned*)(lvs + (rbase + 24) * PAD);   // +24

        #pragma unroll
        for (int ks = 0; ks < 16; ks++) {
            int d0 = ks * 8 + lq;
            unsigned a00 = r0[d0], a01 = r1[d0], a02 = r0[d0 + 4], a03 = r1[d0 + 4];
            unsigned a10 = r2[d0], a11 = r3[d0], a12 = r2[d0 + 4], a13 = r3[d0 + 4];
            #pragma unroll
            for (int ns = 0; ns < 2; ns++) {
                mma_tf32(acc[0][ns][0], acc[0][ns][1], acc[0][ns][2], acc[0][ns][3],
                         a00, a01, a02, a03, Bf[ks][ns][0], Bf[ks][ns][1]);
                mma_tf32(acc[1][ns][0], acc[1][ns][1], acc[1][ns][2], acc[1][ns][3],
                         a10, a11, a12, a13, Bf[ks][ns][0], Bf[ks][ns][1]);
            }
        }

        // ---- epilogue: sum over this warp's 32 rows (= one node)
        float cA = csh[rbase];
        float cB = csh[rbase + 8];
        float cC = csh[rbase + 16];
        float cD = csh[rbase + 24];

        float ps[4];
        #pragma unroll
        for (int ns = 0; ns < 2; ns++) {
            int e0 = wn * 16 + ns * 8 + lq * 2;
            float2 nv0 = *(const float2*)&nvs[rbase * PAD + e0];
            float2 nv1 = *(const float2*)&nvs[(rbase + 8) * PAD + e0];
            float2 nv2 = *(const float2*)&nvs[(rbase + 16) * PAD + e0];
            float2 nv3 = *(const float2*)&nvs[(rbase + 24) * PAD + e0];
            ps[ns * 2 + 0] = sigmoid_tanh(acc[0][ns][0]) * nv0.x * cA +
                             sigmoid_tanh(acc[0][ns][2]) * nv1.x * cB +
                             sigmoid_tanh(acc[1][ns][0]) * nv2.x * cC +
                             sigmoid_tanh(acc[1][ns][2]) * nv3.x * cD;
            ps[ns * 2 + 1] = sigmoid_tanh(acc[0][ns][1]) * nv0.y * cA +
                             sigmoid_tanh(acc[0][ns][3]) * nv1.y * cB +
                             sigmoid_tanh(acc[1][ns][1]) * nv2.y * cC +
                             sigmoid_tanh(acc[1][ns][3]) * nv3.y * cD;
        }
        // reduce over lp (8 lanes sharing same lq)
        #pragma unroll
        for (int o = 4; o <= 16; o <<= 1) {
            #pragma unroll
            for (int i = 0; i < 4; i++)
                ps[i] += __shfl_xor_sync(0xffffffffu, ps[i], o);
        }
        if (lane < 4) {
            int node = p * 2 + wm;
            float* op = out + (size_t)node * D_DIM + wn * 16 + lane * 2;
            #pragma unroll
            for (int ns = 0; ns < 2; ns++) {
                float2 r;
                r.x = fmaxf(ts_pre[ns].x * ps[ns * 2 + 0], 0.0f);
                r.y = fmaxf(ts_pre[ns].y * ps[ns * 2 + 1], 0.0f);
                *(float2*)&op[ns * 8] = r;
            }
        }

        buf ^= 1;
    }
}

// ---------------- launch ----------------------------------------------------
extern "C" void kernel_launch(void* const* d_in, const int* in_sizes, int n_in,
                              void* d_out, int out_size) {
    const float* self_feats = (const float*)d_in[0];
    const float* self_vecs  = (const float*)d_in[1];
    const float* neigh      = (const float*)d_in[2];
    const float* link       = (const float*)d_in[3];
    const float* probs      = (const float*)d_in[4];
    const float* gws        = (const float*)d_in[5];
    const float* gwn        = (const float*)d_in[6];
    const float* gwl        = (const float*)d_in[7];
    const float* Ws         = (const float*)d_in[8];
    const float* Wl         = (const float*)d_in[9];
    float* out = (float*)d_out;

    const int smem_tsf  = (D_DIM * D_DIM + TSF_NODES * D_DIM) * sizeof(float); // 72 KB
    const int smem_main = (4 * 64 * PAD + 64 + 2 * D_DIM) * sizeof(float);     // ~133 KB

    cudaFuncSetAttribute(k_tsf,  cudaFuncAttributeMaxDynamicSharedMemorySize, smem_tsf);
    cudaFuncSetAttribute(k_main, cudaFuncAttributeMaxDynamicSharedMemorySize, smem_main);

    k_tself<<<(N_NODES * 32 + 255) / 256, 256>>>(self_vecs, gws);
    k_tsf<<<N_NODES / TSF_NODES, 256, smem_tsf>>>(self_feats, Ws);
    k_main<<<148, 512, smem_main>>>(neigh, link, probs, gwn, gwl, Wl, out);
}

// round 7
// speedup vs baseline: 1.0033x; 1.0033x over previous
#include <cuda_runtime.h>
#include <math.h>

#define N_NODES 20000
#define K_NB    32
#define D_DIM   128
#define PAD     132   // padded row stride (floats)

// ---------------- scratch (device globals: allocation-free) ----------------
__device__ float g_tsf[(size_t)N_NODES * D_DIM];   // self_feats @ self_weights
__device__ float g_tself[N_NODES];                 // self_vecs . gate_self_w

__device__ __forceinline__ float sigmoid_tanh(float x) {
    float t;
    asm("tanh.approx.f32 %0, %1;" : "=f"(t) : "f"(0.5f * x));
    return fmaf(0.5f, t, 0.5f);
}

__device__ __forceinline__ unsigned f2tf32(float x) {
    unsigned u;
    asm("cvt.rna.tf32.f32 %0, %1;" : "=r"(u) : "f"(x));
    return u;
}

__device__ __forceinline__ void cp16(void* dst, const void* src) {
    unsigned sa = (unsigned)__cvta_generic_to_shared(dst);
    asm volatile("cp.async.cg.shared.global [%0], [%1], 16;\n" :: "r"(sa), "l"(src));
}
__device__ __forceinline__ void cp_commit() {
    asm volatile("cp.async.commit_group;\n");
}
__device__ __forceinline__ void cp_wait0() {
    asm volatile("cp.async.wait_group 0;\n");
}

__device__ __forceinline__ void mma_tf32(float& c0, float& c1, float& c2, float& c3,
                                         unsigned a0, unsigned a1, unsigned a2, unsigned a3,
                                         unsigned b0, unsigned b1) {
    asm volatile(
        "mma.sync.aligned.m16n8k8.row.col.f32.tf32.tf32.f32 "
        "{%0,%1,%2,%3}, {%4,%5,%6,%7}, {%8,%9}, {%0,%1,%2,%3};\n"
        : "+f"(c0), "+f"(c1), "+f"(c2), "+f"(c3)
        : "r"(a0), "r"(a1), "r"(a2), "r"(a3), "r"(b0), "r"(b1));
}

// ---------------- kernel 1: tself[n] = dot(self_vecs[n], gate_self_w) ------
__global__ void k_tself(const float* __restrict__ self_vecs,
                        const float* __restrict__ gws) {
    int gtid = blockIdx.x * blockDim.x + threadIdx.x;
    int node = gtid >> 5;
    int lane = gtid & 31;
    if (node >= N_NODES) return;
    const float4* sv = (const float4*)(self_vecs + (size_t)node * D_DIM);
    const float4* gw = (const float4*)gws;
    float4 a = sv[lane];
    float4 b = __ldg(&gw[lane]);
    float s = a.x * b.x + a.y * b.y + a.z * b.z + a.w * b.w;
    #pragma unroll
    for (int o = 16; o > 0; o >>= 1) s += __shfl_down_sync(0xffffffffu, s, o);
    if (lane == 0) g_tself[node] = s;
}

// ---------------- kernel 2: tsf = self_feats @ self_weights ----------------
#define TSF_NODES 16
__global__ void k_tsf(const float* __restrict__ self_feats,
                      const float* __restrict__ Ws) {
    extern __shared__ float sm[];
    float* Wsh = sm;                       // 128*128
    float* sfs = sm + D_DIM * D_DIM;       // 16*128
    int t = threadIdx.x;

    for (int i = t; i < (D_DIM * D_DIM) / 4; i += 256)
        ((float4*)Wsh)[i] = ((const float4*)Ws)[i];

    int nbase = blockIdx.x * TSF_NODES;
    const float4* gsf = (const float4*)(self_feats + (size_t)nbase * D_DIM);
    for (int i = t; i < (TSF_NODES * D_DIM) / 4; i += 256)
        ((float4*)sfs)[i] = gsf[i];
    __syncthreads();

    int e = t & 127;
    int g = t >> 7;
    float acc[8];
    #pragma unroll
    for (int m = 0; m < 8; m++) acc[m] = 0.0f;

    #pragma unroll 4
    for (int d = 0; d < D_DIM; d++) {
        float w = Wsh[d * D_DIM + e];
        #pragma unroll
        for (int m = 0; m < 8; m++)
            acc[m] = fmaf(w, sfs[(g * 8 + m) * D_DIM + d], acc[m]);
    }
    #pragma unroll
    for (int m = 0; m < 8; m++)
        g_tsf[(size_t)(nbase + g * 8 + m) * D_DIM + e] = acc[m];
}

// ---------------- kernel 3: main fused aggregator --------------------------
// 512 threads = 16 warps, warp grid 2(M) x 8(N). Per iteration: 2 nodes =
// 64 rows(M) x 128 cols(N), K=128. Warp (wm, wn) owns node p*2+wm,
// cols [wn*16, wn*16+16). Bf[16][2][2] = 64 regs: no spill.
__global__ void __launch_bounds__(512, 1)
k_main(const float* __restrict__ neigh,
       const float* __restrict__ link,
       const float* __restrict__ probs,
       const float* __restrict__ gwn,
       const float* __restrict__ gwl,
       const float* __restrict__ Wl,
       float* __restrict__ out) {
    extern __shared__ float sm[];
    float* lvb0 = sm;                           // 64*132
    float* lvb1 = lvb0 + 64 * PAD;
    float* nvb0 = lvb1 + 64 * PAD;
    float* nvb1 = nvb0 + 64 * PAD;
    float* csh  = nvb1 + 64 * PAD;              // 64
    float* gwns = csh + 64;                     // 128
    float* gwls = gwns + D_DIM;                 // 128

    int t = threadIdx.x;
    int warp = t >> 5, lane = t & 31;
    int wm = warp >> 3, wn = warp & 7;          // 2 x 8
    int lp = lane >> 2;                          // 0..7
    int lq = lane & 3;                           // 0..3

    if (t < D_DIM) { gwns[t] = gwn[t]; gwls[t] = gwl[t]; }

    // ---- B fragments (loop-invariant, 64 regs):
    // Bf[ks][ns][0] = tf32(Wl[ks*8+lq][wn*16+ns*8+lp]), [1] = k+4
    unsigned Bf[16][2][2];
    {
        int ncol = wn * 16 + lp;
        #pragma unroll
        for (int ks = 0; ks < 16; ks++)
            #pragma unroll
            for (int ns = 0; ns < 2; ns++) {
                Bf[ks][ns][0] = f2tf32(__ldg(&Wl[(ks * 8 + lq) * D_DIM + ncol + ns * 8]));
                Bf[ks][ns][1] = f2tf32(__ldg(&Wl[(ks * 8 + lq + 4) * D_DIM + ncol + ns * 8]));
            }
    }

    float* lvbuf[2] = {lvb0, lvb1};
    float* nvbuf[2] = {nvb0, nvb1};

    // prologue: first tile -> buffer 0  (64 rows x 32 float4-chunks = 2048)
    {
        int p0 = blockIdx.x;
        if (p0 < N_NODES / 2) {
            #pragma unroll
            for (int j = 0; j < 4; j++) {
                int idx = t + j * 512;
                int row = idx >> 5, c4 = idx & 31;
                size_t gb = (((size_t)p0 * 64 + row) << 7) + c4 * 4;
                cp16(lvb0 + row * PAD + c4 * 4, link + gb);
                cp16(nvb0 + row * PAD + c4 * 4, neigh + gb);
            }
        }
        cp_commit();
    }

    int kk = t >> 3, sub = t & 7;               // gate mapping: 64 rows x 8 subs
    int buf = 0;
    for (int p = blockIdx.x; p < N_NODES / 2; p += gridDim.x) {
        // ---- early prefetch of per-node scalars (cover LDG latency)
        float2 ts_pre[2];
        if (lane < 4) {
            int node = p * 2 + wm;
            #pragma unroll
            for (int ns = 0; ns < 2; ns++)
                ts_pre[ns] = *(const float2*)&g_tsf[(size_t)node * D_DIM +
                                                    wn * 16 + ns * 8 + lane * 2];
        }
        float pr_pre = 0.0f, tslf_pre = 0.0f;
        if (sub == 0) {
            pr_pre = __ldg(&probs[(size_t)p * 64 + kk]);
            tslf_pre = g_tself[p * 2 + (kk >> 5)];
        }

        cp_wait0();
        __syncthreads();                          // tile ready; prev reads done

        // ---- kick next tile into other buffer
        int pn = p + gridDim.x;
        if (pn < N_NODES / 2) {
            float* ld = lvbuf[buf ^ 1];
            float* nd_ = nvbuf[buf ^ 1];
            #pragma unroll
            for (int j = 0; j < 4; j++) {
                int idx = t + j * 512;
                int row = idx >> 5, c4 = idx & 31;
                size_t gb = (((size_t)pn * 64 + row) << 7) + c4 * 4;
                cp16(ld + row * PAD + c4 * 4, link + gb);
                cp16(nd_ + row * PAD + c4 * 4, neigh + gb);
            }
        }
        cp_commit();

        const float* lvs = lvbuf[buf];
        const float* nvs = nvbuf[buf];

        // ---- gate coefficients c[kk] = sigmoid(tself + nv.gwn + lv.gwl)/(prob*K)
        // float4 loads, conflict-free (bank groups 4*kk + 16*(sub&1))
        {
            const float4* lrow = (const float4*)(lvs + kk * PAD + sub * 16);
            const float4* nrow = (const float4*)(nvs + kk * PAD + sub * 16);
            const float4* gl = (const float4*)(gwls + sub * 16);
            const float4* gn = (const float4*)(gwns + sub * 16);
            float s = 0.0f;
            #pragma unroll
            for (int i = 0; i < 4; i++) {
                float4 a = lrow[i], b = gl[i];
                s = fmaf(a.x, b.x, s); s = fmaf(a.y, b.y, s);
                s = fmaf(a.z, b.z, s); s = fmaf(a.w, b.w, s);
                float4 c = nrow[i], d = gn[i];
                s = fmaf(c.x, d.x, s); s = fmaf(c.y, d.y, s);
                s = fmaf(c.z, d.z, s); s = fmaf(c.w, d.w, s);
            }
            s += __shfl_down_sync(0xffffffffu, s, 1, 8);
            s += __shfl_down_sync(0xffffffffu, s, 2, 8);
            s += __shfl_down_sync(0xffffffffu, s, 4, 8);
            if (sub == 0) {
                float g = sigmoid_tanh(tslf_pre + s);
                csh[kk] = __fdividef(g, pr_pre) * (1.0f / (float)K_NB);
            }
        }
        __syncthreads();                          // csh visible

        // ---- tensor-core GEMM: rows wm*32..+32, cols wn*16..+16, K=128
        float acc[2][2][4];
        #pragma unroll
        for (int m = 0; m < 2; m++)
            #pragma unroll
            for (int ns = 0; ns < 2; ns++)
                acc[m][ns][0] = acc[m][ns][1] = acc[m][ns][2] = acc[m][ns][3] = 0.0f;

        int rbase = wm * 32 + lp;
        const unsigned* r0 = (const unsigned*)(lvs + rbase * PAD);          // lp
        const unsigned* r1 = (const unsigned*)(lvs + (rbase + 8) * PAD);    // +8
        const unsigned* r2 = (const unsigned*)(lvs + (rbase + 16) * PAD);   // +16
        const unsigned* r3 = (const unsigned*)(lvs + (rbase + 24) * PAD);   // +24

        #pragma unroll
        for (int ks = 0; ks < 16; ks++) {
            int d0 = ks * 8 + lq;
            unsigned a00 = r0[d0], a01 = r1[d0], a02 = r0[d0 + 4], a03 = r1[d0 + 4];
            unsigned a10 = r2[d0], a11 = r3[d0], a12 = r2[d0 + 4], a13 = r3[d0 + 4];
            #pragma unroll
            for (int ns = 0; ns < 2; ns++) {
                mma_tf32(acc[0][ns][0], acc[0][ns][1], acc[0][ns][2], acc[0][ns][3],
                         a00, a01, a02, a03, Bf[ks][ns][0], Bf[ks][ns][1]);
                mma_tf32(acc[1][ns][0], acc[1][ns][1], acc[1][ns][2], acc[1][ns][3],
                         a10, a11, a12, a13, Bf[ks][ns][0], Bf[ks][ns][1]);
            }
        }

        // ---- epilogue: sum over this warp's 32 rows (= one node)
        float cA = csh[rbase];
        float cB = csh[rbase + 8];
        float cC = csh[rbase + 16];
        float cD = csh[rbase + 24];

        float ps[4];
        #pragma unroll
        for (int ns = 0; ns < 2; ns++) {
            int e0 = wn * 16 + ns * 8 + lq * 2;
            float2 nv0 = *(const float2*)&nvs[rbase * PAD + e0];
            float2 nv1 = *(const float2*)&nvs[(rbase + 8) * PAD + e0];
            float2 nv2 = *(const float2*)&nvs[(rbase + 16) * PAD + e0];
            float2 nv3 = *(const float2*)&nvs[(rbase + 24) * PAD + e0];
            ps[ns * 2 + 0] = sigmoid_tanh(acc[0][ns][0]) * nv0.x * cA +
                             sigmoid_tanh(acc[0][ns][2]) * nv1.x * cB +
                             sigmoid_tanh(acc[1][ns][0]) * nv2.x * cC +
                             sigmoid_tanh(acc[1][ns][2]) * nv3.x * cD;
            ps[ns * 2 + 1] = sigmoid_tanh(acc[0][ns][1]) * nv0.y * cA +
                             sigmoid_tanh(acc[0][ns][3]) * nv1.y * cB +
                             sigmoid_tanh(acc[1][ns][1]) * nv2.y * cC +
                             sigmoid_tanh(acc[1][ns][3]) * nv3.y * cD;
        }
        // reduce over lp (8 lanes sharing same lq)
        #pragma unroll
        for (int o = 4; o <= 16; o <<= 1) {
            #pragma unroll
            for (int i = 0; i < 4; i++)
                ps[i] += __shfl_xor_sync(0xffffffffu, ps[i], o);
        }
        if (lane < 4) {
            int node = p * 2 + wm;
            float* op = out + (size_t)node * D_DIM + wn * 16 + lane * 2;
            #pragma unroll
            for (int ns = 0; ns < 2; ns++) {
                float2 r;
                r.x = fmaxf(ts_pre[ns].x * ps[ns * 2 + 0], 0.0f);
                r.y = fmaxf(ts_pre[ns].y * ps[ns * 2 + 1], 0.0f);
                *(float2*)&op[ns * 8] = r;
            }
        }

        buf ^= 1;
    }
}

// ---------------- launch ----------------------------------------------------
extern "C" void kernel_launch(void* const* d_in, const int* in_sizes, int n_in,
                              void* d_out, int out_size) {
    const float* self_feats = (const float*)d_in[0];
    const float* self_vecs  = (const float*)d_in[1];
    const float* neigh      = (const float*)d_in[2];
    const float* link       = (const float*)d_in[3];
    const float* probs      = (const float*)d_in[4];
    const float* gws        = (const float*)d_in[5];
    const float* gwn        = (const float*)d_in[6];
    const float* gwl        = (const float*)d_in[7];
    const float* Ws         = (const float*)d_in[8];
    const float* Wl         = (const float*)d_in[9];
    float* out = (float*)d_out;

    const int smem_tsf  = (D_DIM * D_DIM + TSF_NODES * D_DIM) * sizeof(float); // 72 KB
    const int smem_main = (4 * 64 * PAD + 64 + 2 * D_DIM) * sizeof(float);     // ~133 KB

    cudaFuncSetAttribute(k_tsf,  cudaFuncAttributeMaxDynamicSharedMemorySize, smem_tsf);
    cudaFuncSetAttribute(k_main, cudaFuncAttributeMaxDynamicSharedMemorySize, smem_main);

    k_tself<<<(N_NODES * 32 + 255) / 256, 256>>>(self_vecs, gws);
    k_tsf<<<N_NODES / TSF_NODES, 256, smem_tsf>>>(self_feats, Ws);
    k_main<<<148, 512, smem_main>>>(neigh, link, probs, gwn, gwl, Wl, out);
}

// round 9
// speedup vs baseline: 1.2387x; 1.2347x over previous
#include <cuda_runtime.h>
#include <math.h>

#define N_NODES 20000
#define K_NB    32
#define D_DIM   128
#define PAD     132   // padded row stride (floats)
#define N_TILES (N_NODES / 2)

// ---------------- scratch (device globals: allocation-free) ----------------
__device__ float g_tsf[(size_t)N_NODES * D_DIM];   // self_feats @ self_weights
__device__ float g_tself[N_NODES];                 // self_vecs . gate_self_w

__device__ __forceinline__ float sigmoid_tanh(float x) {
    float t;
    asm("tanh.approx.f32 %0, %1;" : "=f"(t) : "f"(0.5f * x));
    return fmaf(0.5f, t, 0.5f);
}

__device__ __forceinline__ unsigned f2tf32(float x) {
    unsigned u;
    asm("cvt.rna.tf32.f32 %0, %1;" : "=r"(u) : "f"(x));
    return u;
}

__device__ __forceinline__ void cp16(void* dst, const void* src) {
    unsigned sa = (unsigned)__cvta_generic_to_shared(dst);
    asm volatile("cp.async.cg.shared.global [%0], [%1], 16;\n" :: "r"(sa), "l"(src));
}
__device__ __forceinline__ void cp_commit() {
    asm volatile("cp.async.commit_group;\n");
}
__device__ __forceinline__ void cp_wait0() {
    asm volatile("cp.async.wait_group 0;\n");
}

__device__ __forceinline__ void mma_tf32(float& c0, float& c1, float& c2, float& c3,
                                         unsigned a0, unsigned a1, unsigned a2, unsigned a3,
                                         unsigned b0, unsigned b1) {
    asm volatile(
        "mma.sync.aligned.m16n8k8.row.col.f32.tf32.tf32.f32 "
        "{%0,%1,%2,%3}, {%4,%5,%6,%7}, {%8,%9}, {%0,%1,%2,%3};\n"
        : "+f"(c0), "+f"(c1), "+f"(c2), "+f"(c3)
        : "r"(a0), "r"(a1), "r"(a2), "r"(a3), "r"(b0), "r"(b1));
}

// ---------------- kernel 1: tself[n] = dot(self_vecs[n], gate_self_w) ------
__global__ void k_tself(const float* __restrict__ self_vecs,
                        const float* __restrict__ gws) {
    int gtid = blockIdx.x * blockDim.x + threadIdx.x;
    int node = gtid >> 5;
    int lane = gtid & 31;
    if (node >= N_NODES) return;
    float4 a = ((const float4*)(self_vecs + (size_t)node * D_DIM))[lane];
    float4 b = __ldg(&((const float4*)gws)[lane]);
    float s = a.x * b.x + a.y * b.y + a.z * b.z + a.w * b.w;
    #pragma unroll
    for (int o = 16; o > 0; o >>= 1) s += __shfl_down_sync(0xffffffffu, s, o);
    if (lane == 0) g_tself[node] = s;
}

// ---------------- kernel 2: tsf = self_feats @ self_weights ----------------
#define TSF_NODES 16
__global__ void k_tsf(const float* __restrict__ self_feats,
                      const float* __restrict__ Ws) {
    extern __shared__ float sm[];
    float* Wsh = sm;
    float* sfs = sm + D_DIM * D_DIM;
    int t = threadIdx.x;

    for (int i = t; i < (D_DIM * D_DIM) / 4; i += 256)
        ((float4*)Wsh)[i] = ((const float4*)Ws)[i];

    int nbase = blockIdx.x * TSF_NODES;
    const float4* gsf = (const float4*)(self_feats + (size_t)nbase * D_DIM);
    for (int i = t; i < (TSF_NODES * D_DIM) / 4; i += 256)
        ((float4*)sfs)[i] = gsf[i];
    __syncthreads();

    int e = t & 127;
    int g = t >> 7;
    float acc[8];
    #pragma unroll
    for (int m = 0; m < 8; m++) acc[m] = 0.0f;

    #pragma unroll 4
    for (int d = 0; d < D_DIM; d++) {
        float w = Wsh[d * D_DIM + e];
        #pragma unroll
        for (int m = 0; m < 8; m++)
            acc[m] = fmaf(w, sfs[(g * 8 + m) * D_DIM + d], acc[m]);
    }
    #pragma unroll
    for (int m = 0; m < 8; m++)
        g_tsf[(size_t)(nbase + g * 8 + m) * D_DIM + e] = acc[m];
}

// ---------------- kernel 3: main fused aggregator --------------------------
// 256 threads = 8 warps, warp grid 2(M) x 4(N). Per iteration: 2 nodes =
// 64 rows(M) x 128 cols(N), K=128. Warp (wm, wn) owns node p*2+wm,
// cols [wn*32, wn*32+32). B fragments pre-arranged in smem (fragment order);
// GEMM reads B via conflict-free LDS.128.
__global__ void __launch_bounds__(256, 1)
k_main(const float* __restrict__ neigh,
       const float* __restrict__ link,
       const float* __restrict__ probs,
       const float* __restrict__ gwn,
       const float* __restrict__ gwl,
       const float* __restrict__ Wl,
       float* __restrict__ out) {
    extern __shared__ float sm[];
    float* bfrag = sm;                          // 16384 floats (64 KB)
    float* lvb0  = bfrag + 16384;               // 64*132
    float* lvb1  = lvb0 + 64 * PAD;
    float* nvb0  = lvb1 + 64 * PAD;
    float* nvb1  = nvb0 + 64 * PAD;
    float* csh   = nvb1 + 64 * PAD;             // 64
    float* gwns  = csh + 64;                    // 128
    float* gwls  = gwns + D_DIM;                // 128

    int t = threadIdx.x;
    int warp = t >> 5, lane = t & 31;
    int wm = warp >> 2, wn = warp & 3;          // 2 x 4
    int lp = lane >> 2;                          // 0..7
    int lq = lane & 3;                           // 0..3

    if (t < D_DIM) { gwns[t] = gwn[t]; gwls[t] = gwl[t]; }

    // ---- build B fragments in mma order (one-time):
    // bfrag[((wn*16+ks)*2+nsp)*32 + lane][j]:
    //   j=0: W[8ks+lq  ][wn*32+(2nsp  )*8+lp]
    //   j=1: W[8ks+lq+4][wn*32+(2nsp  )*8+lp]
    //   j=2: W[8ks+lq  ][wn*32+(2nsp+1)*8+lp]
    //   j=3: W[8ks+lq+4][wn*32+(2nsp+1)*8+lp]
    for (int i = t; i < 16384; i += 256) {
        int j    = i & 3;
        int ln   = (i >> 2) & 31;
        int nsp  = (i >> 7) & 1;
        int ks   = (i >> 8) & 15;
        int wnb  = i >> 12;
        int llq  = ln & 3, llp = ln >> 2;
        int ns   = nsp * 2 + (j >> 1);
        int k    = ks * 8 + llq + 4 * (j & 1);
        int n    = wnb * 32 + ns * 8 + llp;
        ((unsigned*)bfrag)[i] = f2tf32(__ldg(&Wl[k * D_DIM + n]));
    }

    float* lvbuf[2] = {lvb0, lvb1};
    float* nvbuf[2] = {nvb0, nvb1};

    // prologue: first tile -> buffer 0
    {
        int p0 = blockIdx.x;
        if (p0 < N_TILES) {
            #pragma unroll
            for (int j = 0; j < 8; j++) {
                int idx = t + j * 256;
                int row = idx >> 5, c4 = idx & 31;
                size_t gb = (((size_t)p0 * 64 + row) << 7) + c4 * 4;
                cp16(lvb0 + row * PAD + c4 * 4, link + gb);
                cp16(nvb0 + row * PAD + c4 * 4, neigh + gb);
            }
        }
        cp_commit();
    }

    int kk = t >> 2, sub = t & 3;               // gate mapping
    int buf = 0;
    for (int p = blockIdx.x; p < N_TILES; p += gridDim.x) {
        // ---- early prefetch of per-node scalars
        float2 ts_pre[4];
        if (lane < 4) {
            int node = p * 2 + wm;
            #pragma unroll
            for (int ns = 0; ns < 4; ns++)
                ts_pre[ns] = *(const float2*)&g_tsf[(size_t)node * D_DIM +
                                                    wn * 32 + ns * 8 + lane * 2];
        }
        float pr_pre = 0.0f, tslf_pre = 0.0f;
        if (sub == 0) {
            pr_pre = __ldg(&probs[(size_t)p * 64 + kk]);
            tslf_pre = g_tself[p * 2 + (kk >> 5)];
        }

        cp_wait0();
        __syncthreads();                          // tile ready; prev reads done

        // ---- kick next tile into other buffer
        int pn = p + gridDim.x;
        if (pn < N_TILES) {
            float* ld = lvbuf[buf ^ 1];
            float* nd_ = nvbuf[buf ^ 1];
            #pragma unroll
            for (int j = 0; j < 8; j++) {
                int idx = t + j * 256;
                int row = idx >> 5, c4 = idx & 31;
                size_t gb = (((size_t)pn * 64 + row) << 7) + c4 * 4;
                cp16(ld + row * PAD + c4 * 4, link + gb);
                cp16(nd_ + row * PAD + c4 * 4, neigh + gb);
            }
        }
        cp_commit();

        const float* lvs = lvbuf[buf];
        const float* nvs = nvbuf[buf];

        // ---- gate coefficients, conflict-free float4 pattern:
        // sub reads cols 8*sub + {0,4} + 32m
        {
            float s = 0.0f;
            const float* lr = lvs + kk * PAD;
            const float* nr = nvs + kk * PAD;
            #pragma unroll
            for (int m = 0; m < 4; m++) {
                int c = 8 * sub + 32 * m;
                float4 a = *(const float4*)(lr + c);
                float4 b = *(const float4*)(gwls + c);
                s = fmaf(a.x, b.x, fmaf(a.y, b.y, fmaf(a.z, b.z, fmaf(a.w, b.w, s))));
                float4 a2 = *(const float4*)(lr + c + 4);
                float4 b2 = *(const float4*)(gwls + c + 4);
                s = fmaf(a2.x, b2.x, fmaf(a2.y, b2.y, fmaf(a2.z, b2.z, fmaf(a2.w, b2.w, s))));
                float4 u = *(const float4*)(nr + c);
                float4 v = *(const float4*)(gwns + c);
                s = fmaf(u.x, v.x, fmaf(u.y, v.y, fmaf(u.z, v.z, fmaf(u.w, v.w, s))));
                float4 u2 = *(const float4*)(nr + c + 4);
                float4 v2 = *(const float4*)(gwns + c + 4);
                s = fmaf(u2.x, v2.x, fmaf(u2.y, v2.y, fmaf(u2.z, v2.z, fmaf(u2.w, v2.w, s))));
            }
            s += __shfl_down_sync(0xffffffffu, s, 1);
            s += __shfl_down_sync(0xffffffffu, s, 2);
            if (sub == 0) {
                float g = sigmoid_tanh(tslf_pre + s);
                csh[kk] = __fdividef(g, pr_pre) * (1.0f / (float)K_NB);
            }
        }
        __syncthreads();                          // csh visible

        // ---- tensor-core GEMM: rows wm*32..+32, cols wn*32..+32, K=128
        float acc0[4][4], acc1[4][4];
        #pragma unroll
        for (int ns = 0; ns < 4; ns++) {
            acc0[ns][0] = acc0[ns][1] = acc0[ns][2] = acc0[ns][3] = 0.0f;
            acc1[ns][0] = acc1[ns][1] = acc1[ns][2] = acc1[ns][3] = 0.0f;
        }

        int rbase = wm * 32 + lp;
        const unsigned* r0 = (const unsigned*)(lvs + rbase * PAD);
        const unsigned* r1 = (const unsigned*)(lvs + (rbase + 8) * PAD);
        const unsigned* r2 = (const unsigned*)(lvs + (rbase + 16) * PAD);
        const unsigned* r3 = (const unsigned*)(lvs + (rbase + 24) * PAD);
        const uint4* bf = (const uint4*)bfrag + (wn * 16) * 2 * 32 + lane;

        #pragma unroll
        for (int ks = 0; ks < 16; ks++) {
            int d0 = ks * 8 + lq;
            unsigned a00 = r0[d0], a01 = r1[d0], a02 = r0[d0 + 4], a03 = r1[d0 + 4];
            unsigned a10 = r2[d0], a11 = r3[d0], a12 = r2[d0 + 4], a13 = r3[d0 + 4];
            uint4 B0 = bf[(ks * 2 + 0) * 32];
            uint4 B1 = bf[(ks * 2 + 1) * 32];
            mma_tf32(acc0[0][0], acc0[0][1], acc0[0][2], acc0[0][3],
                     a00, a01, a02, a03, B0.x, B0.y);
            mma_tf32(acc0[1][0], acc0[1][1], acc0[1][2], acc0[1][3],
                     a00, a01, a02, a03, B0.z, B0.w);
            mma_tf32(acc0[2][0], acc0[2][1], acc0[2][2], acc0[2][3],
                     a00, a01, a02, a03, B1.x, B1.y);
            mma_tf32(acc0[3][0], acc0[3][1], acc0[3][2], acc0[3][3],
                     a00, a01, a02, a03, B1.z, B1.w);
            mma_tf32(acc1[0][0], acc1[0][1], acc1[0][2], acc1[0][3],
                     a10, a11, a12, a13, B0.x, B0.y);
            mma_tf32(acc1[1][0], acc1[1][1], acc1[1][2], acc1[1][3],
                     a10, a11, a12, a13, B0.z, B0.w);
            mma_tf32(acc1[2][0], acc1[2][1], acc1[2][2], acc1[2][3],
                     a10, a11, a12, a13, B1.x, B1.y);
            mma_tf32(acc1[3][0], acc1[3][1], acc1[3][2], acc1[3][3],
                     a10, a11, a12, a13, B1.z, B1.w);
        }

        // ---- epilogue: sum over this warp's 32 rows (= one node)
        float cA = csh[rbase];
        float cB = csh[rbase + 8];
        float cC = csh[rbase + 16];
        float cD = csh[rbase + 24];

        float ps[8];
        #pragma unroll
        for (int ns = 0; ns < 4; ns++) {
            int e0 = wn * 32 + ns * 8 + lq * 2;
            float2 nv0 = *(const float2*)&nvs[rbase * PAD + e0];
            float2 nv1 = *(const float2*)&nvs[(rbase + 8) * PAD + e0];
            float2 nv2 = *(const float2*)&nvs[(rbase + 16) * PAD + e0];
            float2 nv3 = *(const float2*)&nvs[(rbase + 24) * PAD + e0];
            ps[ns * 2 + 0] = sigmoid_tanh(acc0[ns][0]) * nv0.x * cA +
                             sigmoid_tanh(acc0[ns][2]) * nv1.x * cB +
                             sigmoid_tanh(acc1[ns][0]) * nv2.x * cC +
                             sigmoid_tanh(acc1[ns][2]) * nv3.x * cD;
            ps[ns * 2 + 1] = sigmoid_tanh(acc0[ns][1]) * nv0.y * cA +
                             sigmoid_tanh(acc0[ns][3]) * nv1.y * cB +
                             sigmoid_tanh(acc1[ns][1]) * nv2.y * cC +
                             sigmoid_tanh(acc1[ns][3]) * nv3.y * cD;
        }
        #pragma unroll
        for (int o = 4; o <= 16; o <<= 1) {
            #pragma unroll
            for (int i = 0; i < 8; i++)
                ps[i] += __shfl_xor_sync(0xffffffffu, ps[i], o);
        }
        if (lane < 4) {
            int node = p * 2 + wm;
            float* op = out + (size_t)node * D_DIM + wn * 32 + lane * 2;
            #pragma unroll
            for (int ns = 0; ns < 4; ns++) {
                float2 r;
                r.x = fmaxf(ts_pre[ns].x * ps[ns * 2 + 0], 0.0f);
                r.y = fmaxf(ts_pre[ns].y * ps[ns * 2 + 1], 0.0f);
                *(float2*)&op[ns * 8] = r;
            }
        }

        buf ^= 1;
    }
}

// ---------------- launch ----------------------------------------------------
extern "C" void kernel_launch(void* const* d_in, const int* in_sizes, int n_in,
                              void* d_out, int out_size) {
    const float* self_feats = (const float*)d_in[0];
    const float* self_vecs  = (const float*)d_in[1];
    const float* neigh      = (const float*)d_in[2];
    const float* link       = (const float*)d_in[3];
    const float* probs      = (const float*)d_in[4];
    const float* gws        = (const float*)d_in[5];
    const float* gwn        = (const float*)d_in[6];
    const float* gwl        = (const float*)d_in[7];
    const float* Ws         = (const float*)d_in[8];
    const float* Wl         = (const float*)d_in[9];
    float* out = (float*)d_out;

    const int smem_tsf  = (D_DIM * D_DIM + TSF_NODES * D_DIM) * sizeof(float); // 72 KB
    const int smem_main = (16384 + 4 * 64 * PAD + 64 + 2 * D_DIM) *
                          sizeof(float);                                       // ~200 KB

    cudaFuncSetAttribute(k_tsf,  cudaFuncAttributeMaxDynamicSharedMemorySize, smem_tsf);
    cudaFuncSetAttribute(k_main, cudaFuncAttributeMaxDynamicSharedMemorySize, smem_main);

    k_tself<<<(N_NODES * 32 + 255) / 256, 256>>>(self_vecs, gws);
    k_tsf<<<N_NODES / TSF_NODES, 256, smem_tsf>>>(self_feats, Ws);
    k_main<<<148, 256, smem_main>>>(neigh, link, probs, gwn, gwl, Wl, out);
}

// round 10
// speedup vs baseline: 1.3609x; 1.0986x over previous
#include <cuda_runtime.h>
#include <math.h>

#define N_NODES 20000
#define K_NB    32
#define D_DIM   128
#define PAD     132   // padded row stride (floats)
#define N_TILES (N_NODES / 2)

// ---------------- scratch (device globals: allocation-free) ----------------
__device__ float g_tsf[(size_t)N_NODES * D_DIM];   // self_feats @ self_weights
__device__ float g_tself[N_NODES];                 // self_vecs . gate_self_w

__device__ __forceinline__ float sigmoid_tanh(float x) {
    float t;
    asm("tanh.approx.f32 %0, %1;" : "=f"(t) : "f"(0.5f * x));
    return fmaf(0.5f, t, 0.5f);
}

__device__ __forceinline__ unsigned f2tf32(float x) {
    unsigned u;
    asm("cvt.rna.tf32.f32 %0, %1;" : "=r"(u) : "f"(x));
    return u;
}

__device__ __forceinline__ void cp16(void* dst, const void* src) {
    unsigned sa = (unsigned)__cvta_generic_to_shared(dst);
    asm volatile("cp.async.cg.shared.global [%0], [%1], 16;\n" :: "r"(sa), "l"(src));
}
__device__ __forceinline__ void cp_commit() {
    asm volatile("cp.async.commit_group;\n");
}
__device__ __forceinline__ void cp_wait0() {
    asm volatile("cp.async.wait_group 0;\n");
}
__device__ __forceinline__ void cp_wait1() {
    asm volatile("cp.async.wait_group 1;\n");
}

__device__ __forceinline__ void mma_tf32(float& c0, float& c1, float& c2, float& c3,
                                         unsigned a0, unsigned a1, unsigned a2, unsigned a3,
                                         unsigned b0, unsigned b1) {
    asm volatile(
        "mma.sync.aligned.m16n8k8.row.col.f32.tf32.tf32.f32 "
        "{%0,%1,%2,%3}, {%4,%5,%6,%7}, {%8,%9}, {%0,%1,%2,%3};\n"
        : "+f"(c0), "+f"(c1), "+f"(c2), "+f"(c3)
        : "r"(a0), "r"(a1), "r"(a2), "r"(a3), "r"(b0), "r"(b1));
}

// ---------------- kernel 1: tself[n] = dot(self_vecs[n], gate_self_w) ------
__global__ void k_tself(const float* __restrict__ self_vecs,
                        const float* __restrict__ gws) {
    int gtid = blockIdx.x * blockDim.x + threadIdx.x;
    int node = gtid >> 5;
    int lane = gtid & 31;
    if (node >= N_NODES) return;
    float4 a = ((const float4*)(self_vecs + (size_t)node * D_DIM))[lane];
    float4 b = __ldg(&((const float4*)gws)[lane]);
    float s = a.x * b.x + a.y * b.y + a.z * b.z + a.w * b.w;
    #pragma unroll
    for (int o = 16; o > 0; o >>= 1) s += __shfl_down_sync(0xffffffffu, s, o);
    if (lane == 0) g_tself[node] = s;
}

// ---------------- kernel 2: tsf = self_feats @ self_weights ----------------
#define TSF_NODES 16
__global__ void k_tsf(const float* __restrict__ self_feats,
                      const float* __restrict__ Ws) {
    extern __shared__ float sm[];
    float* Wsh = sm;
    float* sfs = sm + D_DIM * D_DIM;
    int t = threadIdx.x;

    for (int i = t; i < (D_DIM * D_DIM) / 4; i += 256)
        ((float4*)Wsh)[i] = ((const float4*)Ws)[i];

    int nbase = blockIdx.x * TSF_NODES;
    const float4* gsf = (const float4*)(self_feats + (size_t)nbase * D_DIM);
    for (int i = t; i < (TSF_NODES * D_DIM) / 4; i += 256)
        ((float4*)sfs)[i] = gsf[i];
    __syncthreads();

    int e = t & 127;
    int g = t >> 7;
    float acc[8];
    #pragma unroll
    for (int m = 0; m < 8; m++) acc[m] = 0.0f;

    #pragma unroll 4
    for (int d = 0; d < D_DIM; d++) {
        float w = Wsh[d * D_DIM + e];
        #pragma unroll
        for (int m = 0; m < 8; m++)
            acc[m] = fmaf(w, sfs[(g * 8 + m) * D_DIM + d], acc[m]);
    }
    #pragma unroll
    for (int m = 0; m < 8; m++)
        g_tsf[(size_t)(nbase + g * 8 + m) * D_DIM + e] = acc[m];
}

// ---------------- k_main building blocks -----------------------------------

__device__ __forceinline__ void prefetch_tile(int p, float* lvd, float* nvd,
                                              const float* link,
                                              const float* neigh, int t) {
    if (p < N_TILES) {
        #pragma unroll
        for (int j = 0; j < 8; j++) {
            int idx = t + j * 256;
            int row = idx >> 5, c4 = idx & 31;
            size_t gb = (((size_t)p * 64 + row) << 7) + c4 * 4;
            cp16(lvd + row * PAD + c4 * 4, link + gb);
            cp16(nvd + row * PAD + c4 * 4, neigh + gb);
        }
    }
    cp_commit();
}

__device__ __forceinline__ void ts_load(int p, int wm, int wn, int lane,
                                        float2 (&ts)[4]) {
    if (lane < 4) {
        int node = p * 2 + wm;
        #pragma unroll
        for (int ns = 0; ns < 4; ns++)
            ts[ns] = *(const float2*)&g_tsf[(size_t)node * D_DIM +
                                            wn * 32 + ns * 8 + lane * 2];
    }
}

// GEMM: rows rbase(+8/16/24), cols wn*32..+32, K=128 -> acc0/acc1
__device__ __forceinline__ void do_gemm(const float* lvs, const uint4* bf,
                                        int rbase, int lq,
                                        float (&acc0)[4][4], float (&acc1)[4][4]) {
    #pragma unroll
    for (int ns = 0; ns < 4; ns++) {
        acc0[ns][0] = acc0[ns][1] = acc0[ns][2] = acc0[ns][3] = 0.0f;
        acc1[ns][0] = acc1[ns][1] = acc1[ns][2] = acc1[ns][3] = 0.0f;
    }
    const unsigned* r0 = (const unsigned*)(lvs + rbase * PAD);
    const unsigned* r1 = (const unsigned*)(lvs + (rbase + 8) * PAD);
    const unsigned* r2 = (const unsigned*)(lvs + (rbase + 16) * PAD);
    const unsigned* r3 = (const unsigned*)(lvs + (rbase + 24) * PAD);

    #pragma unroll
    for (int ks = 0; ks < 16; ks++) {
        int d0 = ks * 8 + lq;
        unsigned a00 = r0[d0], a01 = r1[d0], a02 = r0[d0 + 4], a03 = r1[d0 + 4];
        unsigned a10 = r2[d0], a11 = r3[d0], a12 = r2[d0 + 4], a13 = r3[d0 + 4];
        uint4 B0 = bf[(ks * 2 + 0) * 32];
        uint4 B1 = bf[(ks * 2 + 1) * 32];
        mma_tf32(acc0[0][0], acc0[0][1], acc0[0][2], acc0[0][3], a00, a01, a02, a03, B0.x, B0.y);
        mma_tf32(acc0[1][0], acc0[1][1], acc0[1][2], acc0[1][3], a00, a01, a02, a03, B0.z, B0.w);
        mma_tf32(acc0[2][0], acc0[2][1], acc0[2][2], acc0[2][3], a00, a01, a02, a03, B1.x, B1.y);
        mma_tf32(acc0[3][0], acc0[3][1], acc0[3][2], acc0[3][3], a00, a01, a02, a03, B1.z, B1.w);
        mma_tf32(acc1[0][0], acc1[0][1], acc1[0][2], acc1[0][3], a10, a11, a12, a13, B0.x, B0.y);
        mma_tf32(acc1[1][0], acc1[1][1], acc1[1][2], acc1[1][3], a10, a11, a12, a13, B0.z, B0.w);
        mma_tf32(acc1[2][0], acc1[2][1], acc1[2][2], acc1[2][3], a10, a11, a12, a13, B1.x, B1.y);
        mma_tf32(acc1[3][0], acc1[3][1], acc1[3][2], acc1[3][3], a10, a11, a12, a13, B1.z, B1.w);
    }
}

// gate: write csh[kk] for the 64 rows of tile p (4 threads per row)
__device__ __forceinline__ void do_gate(const float* lvs, const float* nvs,
                                        float* cshT, const float* gwls,
                                        const float* gwns, int kk, int sub,
                                        float pr, float tf) {
    float sA = 0.f, sB = 0.f, sC = 0.f, sD = 0.f;   // 4 chains (16 deep each)
    const float* lr = lvs + kk * PAD;
    const float* nr = nvs + kk * PAD;
    #pragma unroll
    for (int m = 0; m < 4; m++) {
        int c = 8 * sub + 32 * m;
        float4 a = *(const float4*)(lr + c);
        float4 b = *(const float4*)(gwls + c);
        sA = fmaf(a.x, b.x, fmaf(a.y, b.y, fmaf(a.z, b.z, fmaf(a.w, b.w, sA))));
        float4 a2 = *(const float4*)(lr + c + 4);
        float4 b2 = *(const float4*)(gwls + c + 4);
        sB = fmaf(a2.x, b2.x, fmaf(a2.y, b2.y, fmaf(a2.z, b2.z, fmaf(a2.w, b2.w, sB))));
        float4 u = *(const float4*)(nr + c);
        float4 v = *(const float4*)(gwns + c);
        sC = fmaf(u.x, v.x, fmaf(u.y, v.y, fmaf(u.z, v.z, fmaf(u.w, v.w, sC))));
        float4 u2 = *(const float4*)(nr + c + 4);
        float4 v2 = *(const float4*)(gwns + c + 4);
        sD = fmaf(u2.x, v2.x, fmaf(u2.y, v2.y, fmaf(u2.z, v2.z, fmaf(u2.w, v2.w, sD))));
    }
    float s = (sA + sB) + (sC + sD);
    s += __shfl_down_sync(0xffffffffu, s, 1);
    s += __shfl_down_sync(0xffffffffu, s, 2);
    if (sub == 0) {
        float g = sigmoid_tanh(tf + s);
        cshT[kk] = __fdividef(g, pr) * (1.0f / (float)K_NB);
    }
}

// epilogue for tile p: reduce over 32 rows, scale, relu, store
__device__ __forceinline__ void do_epi(int p, const float (&acc0)[4][4],
                                       const float (&acc1)[4][4],
                                       const float* csh, const float* nvs,
                                       const float2 (&ts)[4], float* out,
                                       int rbase, int wm, int wn, int lane, int lq) {
    float cA = csh[rbase];
    float cB = csh[rbase + 8];
    float cC = csh[rbase + 16];
    float cD = csh[rbase + 24];

    float ps[8];
    #pragma unroll
    for (int ns = 0; ns < 4; ns++) {
        int e0 = wn * 32 + ns * 8 + lq * 2;
        float2 nv0 = *(const float2*)&nvs[rbase * PAD + e0];
        float2 nv1 = *(const float2*)&nvs[(rbase + 8) * PAD + e0];
        float2 nv2 = *(const float2*)&nvs[(rbase + 16) * PAD + e0];
        float2 nv3 = *(const float2*)&nvs[(rbase + 24) * PAD + e0];
        ps[ns * 2 + 0] = sigmoid_tanh(acc0[ns][0]) * nv0.x * cA +
                         sigmoid_tanh(acc0[ns][2]) * nv1.x * cB +
                         sigmoid_tanh(acc1[ns][0]) * nv2.x * cC +
                         sigmoid_tanh(acc1[ns][2]) * nv3.x * cD;
        ps[ns * 2 + 1] = sigmoid_tanh(acc0[ns][1]) * nv0.y * cA +
                         sigmoid_tanh(acc0[ns][3]) * nv1.y * cB +
                         sigmoid_tanh(acc1[ns][1]) * nv2.y * cC +
                         sigmoid_tanh(acc1[ns][3]) * nv3.y * cD;
    }
    #pragma unroll
    for (int o = 4; o <= 16; o <<= 1) {
        #pragma unroll
        for (int i = 0; i < 8; i++)
            ps[i] += __shfl_xor_sync(0xffffffffu, ps[i], o);
    }
    if (lane < 4) {
        int node = p * 2 + wm;
        float* op = out + (size_t)node * D_DIM + wn * 32 + lane * 2;
        #pragma unroll
        for (int ns = 0; ns < 4; ns++) {
            float2 r;
            r.x = fmaxf(ts[ns].x * ps[ns * 2 + 0], 0.0f);
            r.y = fmaxf(ts[ns].y * ps[ns * 2 + 1], 0.0f);
            *(float2*)&op[ns * 8] = r;
        }
    }
}

// ---------------- kernel 3: main (software-pipelined) ----------------------
// 256 threads = 8 warps, warp grid 2(M) x 4(N). Tile = 2 nodes (64 rows).
// Pipeline: GEMM(p) issued, epilogue(p-1) + gate(p) overlap the tensor drain;
// acc ping-pong gives HMMA a full iteration to complete.
__global__ void __launch_bounds__(256, 1)
k_main(const float* __restrict__ neigh,
       const float* __restrict__ link,
       const float* __restrict__ probs,
       const float* __restrict__ gwn,
       const float* __restrict__ gwl,
       const float* __restrict__ Wl,
       float* __restrict__ out) {
    extern __shared__ float sm[];
    float* bfrag = sm;                          // 16384 floats (64 KB)
    float* lvb0  = bfrag + 16384;               // 64*132
    float* lvb1  = lvb0 + 64 * PAD;
    float* nvb0  = lvb1 + 64 * PAD;
    float* nvb1  = nvb0 + 64 * PAD;
    float* csh0  = nvb1 + 64 * PAD;             // 64
    float* csh1  = csh0 + 64;                   // 64
    float* gwns  = csh1 + 64;                   // 128
    float* gwls  = gwns + D_DIM;                // 128

    int t = threadIdx.x;
    int warp = t >> 5, lane = t & 31;
    int wm = warp >> 2, wn = warp & 3;          // 2 x 4
    int lp = lane >> 2;
    int lq = lane & 3;
    int rbase = wm * 32 + lp;
    int kk = t >> 2, sub = t & 3;
    int G = gridDim.x;

    if (t < D_DIM) { gwns[t] = gwn[t]; gwls[t] = gwl[t]; }

    // ---- build B fragments in mma order (one-time), as R9
    for (int i = t; i < 16384; i += 256) {
        int j    = i & 3;
        int ln   = (i >> 2) & 31;
        int nsp  = (i >> 7) & 1;
        int ks   = (i >> 8) & 15;
        int wnb  = i >> 12;
        int llq  = ln & 3, llp = ln >> 2;
        int ns   = nsp * 2 + (j >> 1);
        int k    = ks * 8 + llq + 4 * (j & 1);
        int n    = wnb * 32 + ns * 8 + llp;
        ((unsigned*)bfrag)[i] = f2tf32(__ldg(&Wl[k * D_DIM + n]));
    }
    const uint4* bf = (const uint4*)bfrag + (wn * 16) * 2 * 32 + lane;

    float accA0[4][4], accA1[4][4], accB0[4][4], accB1[4][4];
    float2 ts_prev[4];

    // ---- prologue: tiles p0 -> buf0, p0+G -> buf1
    int p0 = blockIdx.x;
    prefetch_tile(p0, lvb0, nvb0, link, neigh, t);
    prefetch_tile(p0 + G, lvb1, nvb1, link, neigh, t);
    cp_wait1();
    __syncthreads();                // tile p0 ready; bfrag/gw visible

    {
        float pr = 0.f, tf = 0.f;
        if (sub == 0) {
            pr = __ldg(&probs[(size_t)p0 * 64 + kk]);
            tf = g_tself[p0 * 2 + (kk >> 5)];
        }
        do_gemm(lvb0, bf, rbase, lq, accA0, accA1);
        do_gate(lvb0, nvb0, csh0, gwls, gwns, kk, sub, pr, tf);
        ts_load(p0, wm, wn, lane, ts_prev);
    }

    int p = p0;
    int phase = 0;     // 0: pending epilogue = accA/csh0/nvb0; next GEMM buf = 1
    for (int pn = p0 + G; pn < N_TILES; pn += G) {
        if (phase == 0) {
            cp_wait0();
            __syncthreads();                     // tile pn (buf1) ready
            float pr = 0.f, tf = 0.f;
            if (sub == 0) {
                pr = __ldg(&probs[(size_t)pn * 64 + kk]);
                tf = g_tself[pn * 2 + (kk >> 5)];
            }
            do_gemm(lvb1, bf, rbase, lq, accB0, accB1);       // tensor: tile pn
            do_epi(p, accA0, accA1, csh0, nvb0, ts_prev, out, // overlaps drain
                   rbase, wm, wn, lane, lq);
            __syncthreads();                     // nvb0/csh0 reads done
            prefetch_tile(pn + G, lvb0, nvb0, link, neigh, t);
            do_gate(lvb1, nvb1, csh1, gwls, gwns, kk, sub, pr, tf);
            ts_load(pn, wm, wn, lane, ts_prev);
        } else {
            cp_wait0();
            __syncthreads();                     // tile pn (buf0) ready
            float pr = 0.f, tf = 0.f;
            if (sub == 0) {
                pr = __ldg(&probs[(size_t)pn * 64 + kk]);
                tf = g_tself[pn * 2 + (kk >> 5)];
            }
            do_gemm(lvb0, bf, rbase, lq, accA0, accA1);
            do_epi(p, accB0, accB1, csh1, nvb1, ts_prev, out,
                   rbase, wm, wn, lane, lq);
            __syncthreads();
            prefetch_tile(pn + G, lvb1, nvb1, link, neigh, t);
            do_gate(lvb0, nvb0, csh0, gwls, gwns, kk, sub, pr, tf);
            ts_load(pn, wm, wn, lane, ts_prev);
        }
        p = pn;
        phase ^= 1;
    }

    __syncthreads();                             // last gate's csh visible
    if (phase == 0)
        do_epi(p, accA0, accA1, csh0, nvb0, ts_prev, out, rbase, wm, wn, lane, lq);
    else
        do_epi(p, accB0, accB1, csh1, nvb1, ts_prev, out, rbase, wm, wn, lane, lq);
}

// ---------------- launch ----------------------------------------------------
extern "C" void kernel_launch(void* const* d_in, const int* in_sizes, int n_in,
                              void* d_out, int out_size) {
    const float* self_feats = (const float*)d_in[0];
    const float* self_vecs  = (const float*)d_in[1];
    const float* neigh      = (const float*)d_in[2];
    const float* link       = (const float*)d_in[3];
    const float* probs      = (const float*)d_in[4];
    const float* gws        = (const float*)d_in[5];
    const float* gwn        = (const float*)d_in[6];
    const float* gwl        = (const float*)d_in[7];
    const float* Ws         = (const float*)d_in[8];
    const float* Wl         = (const float*)d_in[9];
    float* out = (float*)d_out;

    const int smem_tsf  = (D_DIM * D_DIM + TSF_NODES * D_DIM) * sizeof(float); // 72 KB
    const int smem_main = (16384 + 4 * 64 * PAD + 2 * 64 + 2 * D_DIM) *
                          sizeof(float);                                       // ~200 KB

    cudaFuncSetAttribute(k_tsf,  cudaFuncAttributeMaxDynamicSharedMemorySize, smem_tsf);
    cudaFuncSetAttribute(k_main, cudaFuncAttributeMaxDynamicSharedMemorySize, smem_main);

    k_tself<<<(N_NODES * 32 + 255) / 256, 256>>>(self_vecs, gws);
    k_tsf<<<N_NODES / TSF_NODES, 256, smem_tsf>>>(self_feats, Ws);
    k_main<<<148, 256, smem_main>>>(neigh, link, probs, gwn, gwl, Wl, out);
}

// round 11
// speedup vs baseline: 1.4942x; 1.0980x over previous
#include <cuda_runtime.h>
#include <math.h>

#define N_NODES 20000
#define K_NB    32
#define D_DIM   128
#define PAD     132   // fp32 tile row stride (floats)
#define AHP     68    // fp16 A-tile row stride (u32)
#define N_TILES (N_NODES / 2)

// ---------------- scratch (device globals: allocation-free) ----------------
__device__ float g_tsf[(size_t)N_NODES * D_DIM];   // self_feats @ self_weights
__device__ float g_tself[N_NODES];                 // self_vecs . gate_self_w

__device__ __forceinline__ float sigmoid_tanh(float x) {
    float t;
    asm("tanh.approx.f32 %0, %1;" : "=f"(t) : "f"(0.5f * x));
    return fmaf(0.5f, t, 0.5f);
}

// pack two f32 -> f16x2 (lo = second arg)
__device__ __forceinline__ unsigned packh(float hi, float lo) {
    unsigned r;
    asm("cvt.rn.f16x2.f32 %0, %1, %2;" : "=r"(r) : "f"(hi), "f"(lo));
    return r;
}

__device__ __forceinline__ void cp16(void* dst, const void* src) {
    unsigned sa = (unsigned)__cvta_generic_to_shared(dst);
    asm volatile("cp.async.cg.shared.global [%0], [%1], 16;\n" :: "r"(sa), "l"(src));
}
__device__ __forceinline__ void cp_commit() {
    asm volatile("cp.async.commit_group;\n");
}
__device__ __forceinline__ void cp_wait0() {
    asm volatile("cp.async.wait_group 0;\n");
}

// fp16 mma m16n8k16, fp32 accumulate
__device__ __forceinline__ void mma_f16(float& c0, float& c1, float& c2, float& c3,
                                        unsigned a0, unsigned a1, unsigned a2, unsigned a3,
                                        unsigned b0, unsigned b1) {
    asm volatile(
        "mma.sync.aligned.m16n8k16.row.col.f32.f16.f16.f32 "
        "{%0,%1,%2,%3}, {%4,%5,%6,%7}, {%8,%9}, {%0,%1,%2,%3};\n"
        : "+f"(c0), "+f"(c1), "+f"(c2), "+f"(c3)
        : "r"(a0), "r"(a1), "r"(a2), "r"(a3), "r"(b0), "r"(b1));
}

// ---------------- kernel 1: tself[n] = dot(self_vecs[n], gate_self_w) ------
__global__ void k_tself(const float* __restrict__ self_vecs,
                        const float* __restrict__ gws) {
    int gtid = blockIdx.x * blockDim.x + threadIdx.x;
    int node = gtid >> 5;
    int lane = gtid & 31;
    if (node >= N_NODES) return;
    float4 a = ((const float4*)(self_vecs + (size_t)node * D_DIM))[lane];
    float4 b = __ldg(&((const float4*)gws)[lane]);
    float s = a.x * b.x + a.y * b.y + a.z * b.z + a.w * b.w;
    #pragma unroll
    for (int o = 16; o > 0; o >>= 1) s += __shfl_down_sync(0xffffffffu, s, o);
    if (lane == 0) g_tself[node] = s;
}

// ---------------- kernel 2: tsf = self_feats @ self_weights ----------------
#define TSF_NODES 16
__global__ void k_tsf(const float* __restrict__ self_feats,
                      const float* __restrict__ Ws) {
    extern __shared__ float sm[];
    float* Wsh = sm;
    float* sfs = sm + D_DIM * D_DIM;
    int t = threadIdx.x;

    for (int i = t; i < (D_DIM * D_DIM) / 4; i += 256)
        ((float4*)Wsh)[i] = ((const float4*)Ws)[i];

    int nbase = blockIdx.x * TSF_NODES;
    const float4* gsf = (const float4*)(self_feats + (size_t)nbase * D_DIM);
    for (int i = t; i < (TSF_NODES * D_DIM) / 4; i += 256)
        ((float4*)sfs)[i] = gsf[i];
    __syncthreads();

    int e = t & 127;
    int g = t >> 7;
    float acc[8];
    #pragma unroll
    for (int m = 0; m < 8; m++) acc[m] = 0.0f;

    #pragma unroll 4
    for (int d = 0; d < D_DIM; d++) {
        float w = Wsh[d * D_DIM + e];
        #pragma unroll
        for (int m = 0; m < 8; m++)
            acc[m] = fmaf(w, sfs[(g * 8 + m) * D_DIM + d], acc[m]);
    }
    #pragma unroll
    for (int m = 0; m < 8; m++)
        g_tsf[(size_t)(nbase + g * 8 + m) * D_DIM + e] = acc[m];
}

// ---------------- k_main building blocks -----------------------------------

__device__ __forceinline__ void prefetch_lv(int p, float* lvd,
                                            const float* link, int t) {
    if (p < N_TILES) {
        #pragma unroll
        for (int j = 0; j < 8; j++) {
            int idx = t + j * 256;
            int row = idx >> 5, c4 = idx & 31;
            size_t gb = (((size_t)p * 64 + row) << 7) + c4 * 4;
            cp16(lvd + row * PAD + c4 * 4, link + gb);
        }
    }
    cp_commit();
}
__device__ __forceinline__ void prefetch_nv(int p, float* nvd,
                                            const float* neigh, int t) {
    if (p < N_TILES) {
        #pragma unroll
        for (int j = 0; j < 8; j++) {
            int idx = t + j * 256;
            int row = idx >> 5, c4 = idx & 31;
            size_t gb = (((size_t)p * 64 + row) << 7) + c4 * 4;
            cp16(nvd + row * PAD + c4 * 4, neigh + gb);
        }
    }
    cp_commit();
}

__device__ __forceinline__ void ts_load(int p, int wm, int wn, int lane,
                                        float2 (&ts)[4]) {
    if (lane < 4) {
        int node = p * 2 + wm;
        #pragma unroll
        for (int ns = 0; ns < 4; ns++)
            ts[ns] = *(const float2*)&g_tsf[(size_t)node * D_DIM +
                                            wn * 32 + ns * 8 + lane * 2];
    }
}

// gate + fp16 conversion of lv into ah (A tile), fused single pass
__device__ __forceinline__ void do_gatec(const float* lvs, const float* nvs,
                                         unsigned* ah, float* cshT,
                                         const float* gwls, const float* gwns,
                                         int kk, int sub, float pr, float tf) {
    float sA = 0.f, sB = 0.f, sC = 0.f, sD = 0.f;
    const float* lr = lvs + kk * PAD;
    const float* nr = nvs + kk * PAD;
    unsigned* ar = ah + kk * AHP;
    #pragma unroll
    for (int m = 0; m < 4; m++) {
        int c = 8 * sub + 32 * m;
        float4 a = *(const float4*)(lr + c);
        float4 b = *(const float4*)(gwls + c);
        sA = fmaf(a.x, b.x, fmaf(a.y, b.y, fmaf(a.z, b.z, fmaf(a.w, b.w, sA))));
        float4 a2 = *(const float4*)(lr + c + 4);
        float4 b2 = *(const float4*)(gwls + c + 4);
        sB = fmaf(a2.x, b2.x, fmaf(a2.y, b2.y, fmaf(a2.z, b2.z, fmaf(a2.w, b2.w, sB))));
        uint4 ph;
        ph.x = packh(a.y, a.x);
        ph.y = packh(a.w, a.z);
        ph.z = packh(a2.y, a2.x);
        ph.w = packh(a2.w, a2.z);
        *(uint4*)(ar + (c >> 1)) = ph;
        float4 u = *(const float4*)(nr + c);
        float4 v = *(const float4*)(gwns + c);
        sC = fmaf(u.x, v.x, fmaf(u.y, v.y, fmaf(u.z, v.z, fmaf(u.w, v.w, sC))));
        float4 u2 = *(const float4*)(nr + c + 4);
        float4 v2 = *(const float4*)(gwns + c + 4);
        sD = fmaf(u2.x, v2.x, fmaf(u2.y, v2.y, fmaf(u2.z, v2.z, fmaf(u2.w, v2.w, sD))));
    }
    float s = (sA + sB) + (sC + sD);
    s += __shfl_down_sync(0xffffffffu, s, 1);
    s += __shfl_down_sync(0xffffffffu, s, 2);
    if (sub == 0) {
        float g = sigmoid_tanh(tf + s);
        cshT[kk] = __fdividef(g, pr) * (1.0f / (float)K_NB);
    }
}

// fp16 GEMM: rows rbase(+8/16/24), cols wn*32..+32, K=128 (8 k16 steps)
__device__ __forceinline__ void do_gemm(const unsigned* ah, const uint4* bf,
                                        int rbase, int lq,
                                        float (&acc0)[4][4], float (&acc1)[4][4]) {
    #pragma unroll
    for (int ns = 0; ns < 4; ns++) {
        acc0[ns][0] = acc0[ns][1] = acc0[ns][2] = acc0[ns][3] = 0.0f;
        acc1[ns][0] = acc1[ns][1] = acc1[ns][2] = acc1[ns][3] = 0.0f;
    }
    const unsigned* r0 = ah + rbase * AHP;
    const unsigned* r1 = ah + (rbase + 8) * AHP;
    const unsigned* r2 = ah + (rbase + 16) * AHP;
    const unsigned* r3 = ah + (rbase + 24) * AHP;

    #pragma unroll
    for (int ks = 0; ks < 8; ks++) {
        int d0 = ks * 8 + lq;
        unsigned a00 = r0[d0], a01 = r1[d0], a02 = r0[d0 + 4], a03 = r1[d0 + 4];
        unsigned a10 = r2[d0], a11 = r3[d0], a12 = r2[d0 + 4], a13 = r3[d0 + 4];
        uint4 B0 = bf[(ks * 2 + 0) * 32];
        uint4 B1 = bf[(ks * 2 + 1) * 32];
        mma_f16(acc0[0][0], acc0[0][1], acc0[0][2], acc0[0][3], a00, a01, a02, a03, B0.x, B0.y);
        mma_f16(acc0[1][0], acc0[1][1], acc0[1][2], acc0[1][3], a00, a01, a02, a03, B0.z, B0.w);
        mma_f16(acc0[2][0], acc0[2][1], acc0[2][2], acc0[2][3], a00, a01, a02, a03, B1.x, B1.y);
        mma_f16(acc0[3][0], acc0[3][1], acc0[3][2], acc0[3][3], a00, a01, a02, a03, B1.z, B1.w);
        mma_f16(acc1[0][0], acc1[0][1], acc1[0][2], acc1[0][3], a10, a11, a12, a13, B0.x, B0.y);
        mma_f16(acc1[1][0], acc1[1][1], acc1[1][2], acc1[1][3], a10, a11, a12, a13, B0.z, B0.w);
        mma_f16(acc1[2][0], acc1[2][1], acc1[2][2], acc1[2][3], a10, a11, a12, a13, B1.x, B1.y);
        mma_f16(acc1[3][0], acc1[3][1], acc1[3][2], acc1[3][3], a10, a11, a12, a13, B1.z, B1.w);
    }
}

// epilogue for tile p: reduce over 32 rows, scale, relu, store
__device__ __forceinline__ void do_epi(int p, const float (&acc0)[4][4],
                                       const float (&acc1)[4][4],
                                       const float* csh, const float* nvs,
                                       const float2 (&ts)[4], float* out,
                                       int rbase, int wm, int wn, int lane, int lq) {
    float cA = csh[rbase];
    float cB = csh[rbase + 8];
    float cC = csh[rbase + 16];
    float cD = csh[rbase + 24];

    float ps[8];
    #pragma unroll
    for (int ns = 0; ns < 4; ns++) {
        int e0 = wn * 32 + ns * 8 + lq * 2;
        float2 nv0 = *(const float2*)&nvs[rbase * PAD + e0];
        float2 nv1 = *(const float2*)&nvs[(rbase + 8) * PAD + e0];
        float2 nv2 = *(const float2*)&nvs[(rbase + 16) * PAD + e0];
        float2 nv3 = *(const float2*)&nvs[(rbase + 24) * PAD + e0];
        ps[ns * 2 + 0] = sigmoid_tanh(acc0[ns][0]) * nv0.x * cA +
                         sigmoid_tanh(acc0[ns][2]) * nv1.x * cB +
                         sigmoid_tanh(acc1[ns][0]) * nv2.x * cC +
                         sigmoid_tanh(acc1[ns][2]) * nv3.x * cD;
        ps[ns * 2 + 1] = sigmoid_tanh(acc0[ns][1]) * nv0.y * cA +
                         sigmoid_tanh(acc0[ns][3]) * nv1.y * cB +
                         sigmoid_tanh(acc1[ns][1]) * nv2.y * cC +
                         sigmoid_tanh(acc1[ns][3]) * nv3.y * cD;
    }
    #pragma unroll
    for (int o = 4; o <= 16; o <<= 1) {
        #pragma unroll
        for (int i = 0; i < 8; i++)
            ps[i] += __shfl_xor_sync(0xffffffffu, ps[i], o);
    }
    if (lane < 4) {
        int node = p * 2 + wm;
        float* op = out + (size_t)node * D_DIM + wn * 32 + lane * 2;
        #pragma unroll
        for (int ns = 0; ns < 4; ns++) {
            float2 r;
            r.x = fmaxf(ts[ns].x * ps[ns * 2 + 0], 0.0f);
            r.y = fmaxf(ts[ns].y * ps[ns * 2 + 1], 0.0f);
            *(float2*)&op[ns * 8] = r;
        }
    }
}

// ---------------- kernel 3: main (fp16 tensor, pipelined) ------------------
// 256 threads = 8 warps, warp grid 2(M) x 4(N). Tile = 2 nodes (64 rows).
// Order per iter: gate+convert(p) -> GEMM(p) -> epilogue(p-1) overlapping
// the HMMA drain; acc/csh ping-pong; lv single-buffered, nv double-buffered.
__global__ void __launch_bounds__(256, 1)
k_main(const float* __restrict__ neigh,
       const float* __restrict__ link,
       const float* __restrict__ probs,
       const float* __restrict__ gwn,
       const float* __restrict__ gwl,
       const float* __restrict__ Wl,
       float* __restrict__ out) {
    extern __shared__ float sm[];
    float*    bfrag = sm;                          // 8192 u32 (32 KB)
    float*    lvb   = bfrag + 8192;                // 64*132
    float*    nvb0  = lvb + 64 * PAD;
    float*    nvb1  = nvb0 + 64 * PAD;
    unsigned* ah    = (unsigned*)(nvb1 + 64 * PAD);// 64*68 u32 (17 KB)
    float*    csh0  = (float*)(ah + 64 * AHP);     // 64
    float*    csh1  = csh0 + 64;                   // 64
    float*    gwns  = csh1 + 64;                   // 128
    float*    gwls  = gwns + D_DIM;                // 128

    int t = threadIdx.x;
    int warp = t >> 5, lane = t & 31;
    int wm = warp >> 2, wn = warp & 3;
    int lp = lane >> 2;
    int lq = lane & 3;
    int rbase = wm * 32 + lp;
    int kk = t >> 2, sub = t & 3;
    int G = gridDim.x;

    // ---- prologue prefetch of tile p0 (lv + nv0)
    int p0 = blockIdx.x;
    if (p0 < N_TILES) {
        #pragma unroll
        for (int j = 0; j < 8; j++) {
            int idx = t + j * 256;
            int row = idx >> 5, c4 = idx & 31;
            size_t gb = (((size_t)p0 * 64 + row) << 7) + c4 * 4;
            cp16(lvb + row * PAD + c4 * 4, link + gb);
            cp16(nvb0 + row * PAD + c4 * 4, neigh + gb);
        }
    }
    cp_commit();

    if (t < D_DIM) { gwns[t] = gwn[t]; gwls[t] = gwl[t]; }

    // ---- build fp16 B fragments in mma order (one-time, 8192 u32)
    // uint4 f = ((wnb*8+ks)*2+nsp)*32+ln; element j of f:
    //   ns = 2nsp + (j>>1);  kb = 16ks + 2*llq + 8*(j&1);  n = wnb*32+ns*8+llp
    //   val = pack(W[kb+1][n] hi, W[kb][n] lo)
    for (int i = t; i < 8192; i += 256) {
        int j   = i & 3;
        int ln  = (i >> 2) & 31;
        int nsp = (i >> 7) & 1;
        int ks  = (i >> 8) & 7;
        int wnb = (i >> 11) & 3;
        int llq = ln & 3, llp = ln >> 2;
        int ns  = 2 * nsp + (j >> 1);
        int kb  = ks * 16 + 2 * llq + 8 * (j & 1);
        int n   = wnb * 32 + ns * 8 + llp;
        ((unsigned*)bfrag)[i] = packh(__ldg(&Wl[(kb + 1) * D_DIM + n]),
                                      __ldg(&Wl[kb * D_DIM + n]));
    }
    const uint4* bf = (const uint4*)bfrag + (wn * 8) * 2 * 32 + lane;

    float accA0[4][4], accA1[4][4], accB0[4][4], accB1[4][4];
    float2 ts_prev[4];

    // ---- prologue compute for tile p0
    {
        float pr = 0.f, tf = 0.f;
        if (sub == 0) {
            pr = __ldg(&probs[(size_t)p0 * 64 + kk]);
            tf = g_tself[p0 * 2 + (kk >> 5)];
        }
        cp_wait0();
        __syncthreads();                 // tile p0 + bfrag + gw ready
        do_gatec(lvb, nvb0, ah, csh0, gwls, gwns, kk, sub, pr, tf);
        __syncthreads();                 // ah/csh0 visible; lv free
        prefetch_lv(p0 + G, lvb, link, t);
        do_gemm(ah, bf, rbase, lq, accA0, accA1);
        ts_load(p0, wm, wn, lane, ts_prev);
        prefetch_nv(p0 + G, nvb1, neigh, t);
    }

    int p = p0;
    int phase = 1;     // phase of the NEXT tile (pn): 1 -> nv1/csh1/accB
    for (int pn = p0 + G; pn < N_TILES; pn += G) {
        float pr = 0.f, tf = 0.f;
        if (sub == 0) {
            pr = __ldg(&probs[(size_t)pn * 64 + kk]);
            tf = g_tself[pn * 2 + (kk >> 5)];
        }
        cp_wait0();
        __syncthreads();                 // tile pn (lv + nv[phase]) ready
        if (phase) {
            do_gatec(lvb, nvb1, ah, csh1, gwls, gwns, kk, sub, pr, tf);
            __syncthreads();             // ah/csh1 visible; lv free
            prefetch_lv(pn + G, lvb, link, t);
            do_gemm(ah, bf, rbase, lq, accB0, accB1);
            do_epi(p, accA0, accA1, csh0, nvb0, ts_prev, out,
                   rbase, wm, wn, lane, lq);
            ts_load(pn, wm, wn, lane, ts_prev);
            __syncthreads();             // nvb0/csh0 reads done
            prefetch_nv(pn + G, nvb0, neigh, t);
        } else {
            do_gatec(lvb, nvb0, ah, csh0, gwls, gwns, kk, sub, pr, tf);
            __syncthreads();
            prefetch_lv(pn + G, lvb, link, t);
            do_gemm(ah, bf, rbase, lq, accA0, accA1);
            do_epi(p, accB0, accB1, csh1, nvb1, ts_prev, out,
                   rbase, wm, wn, lane, lq);
            ts_load(pn, wm, wn, lane, ts_prev);
            __syncthreads();
            prefetch_nv(pn + G, nvb1, neigh, t);
        }
        p = pn;
        phase ^= 1;
    }

    // final pending epilogue: last tile used phase^1
    if (phase)
        do_epi(p, accA0, accA1, csh0, nvb0, ts_prev, out, rbase, wm, wn, lane, lq);
    else
        do_epi(p, accB0, accB1, csh1, nvb1, ts_prev, out, rbase, wm, wn, lane, lq);
}

// ---------------- launch ----------------------------------------------------
extern "C" void kernel_launch(void* const* d_in, const int* in_sizes, int n_in,
                              void* d_out, int out_size) {
    const float* self_feats = (const float*)d_in[0];
    const float* self_vecs  = (const float*)d_in[1];
    const float* neigh      = (const float*)d_in[2];
    const float* link       = (const float*)d_in[3];
    const float* probs      = (const float*)d_in[4];
    const float* gws        = (const float*)d_in[5];
    const float* gwn        = (const float*)d_in[6];
    const float* gwl        = (const float*)d_in[7];
    const float* Ws         = (const float*)d_in[8];
    const float* Wl         = (const float*)d_in[9];
    float* out = (float*)d_out;

    const int smem_tsf  = (D_DIM * D_DIM + TSF_NODES * D_DIM) * sizeof(float); // 72 KB
    const int smem_main = (8192 + 3 * 64 * PAD + 64 * AHP + 2 * 64 +
                           2 * D_DIM) * sizeof(float);                         // ~153 KB

    cudaFuncSetAttribute(k_tsf,  cudaFuncAttributeMaxDynamicSharedMemorySize, smem_tsf);
    cudaFuncSetAttribute(k_main, cudaFuncAttributeMaxDynamicSharedMemorySize, smem_main);

    k_tself<<<(N_NODES * 32 + 255) / 256, 256>>>(self_vecs, gws);
    k_tsf<<<N_NODES / TSF_NODES, 256, smem_tsf>>>(self_feats, Ws);
    k_main<<<148, 256, smem_main>>>(neigh, link, probs, gwn, gwl, Wl, out);
}